// round 11
// baseline (speedup 1.0000x reference)
#include <cuda_runtime.h>

#define NB    2048
#define NE    30
#define NA    38
#define NN    8
#define BASIS 32
#define KD    64
#define ED    128
#define HK    45
#define HO    91
#define NL    3

typedef unsigned long long ull;
typedef unsigned int uint32;

__device__ float g_xs [NB * NE * ED];

// Prepacked tf32 B-fragments (fragment order), filled once by k_prepack.
__device__ uint2 g_B1f[NL][6 * 4 * 32];     // msg w1  [nt6][kt4][lane]
__device__ uint2 g_B2f[NL][8 * 6 * 32];     // msg w2  [nt8][kt6][lane]
__device__ uint2 g_B1o[NL][12 * 8 * 32];    // out W1  [nt12][kt8][lane]
__device__ uint2 g_B2o[NL][16 * 12 * 32];   // out W2  [nt16][kt12][lane]

__device__ __forceinline__ float ssp(float x) {
    float t = __expf(-fabsf(x));
    return fmaxf(x, 0.f) + __logf(1.f + t) - 0.69314718055994530942f;
}
__device__ __forceinline__ ull ffma2(ull a, ull b, ull c) {
    ull d; asm("fma.rn.f32x2 %0, %1, %2, %3;" : "=l"(d) : "l"(a), "l"(b), "l"(c));
    return d;
}
__device__ __forceinline__ ull pack2(float x, float y) {
    ull r; asm("mov.b64 %0, {%1, %2};" : "=l"(r) : "f"(x), "f"(y)); return r;
}
__device__ __forceinline__ ull dup2(float x) { return pack2(x, x); }
__device__ __forceinline__ float2 unpack2(ull v) {
    float2 r; asm("mov.b64 {%0, %1}, %2;" : "=f"(r.x), "=f"(r.y) : "l"(v)); return r;
}
__device__ __forceinline__ ull ldsu64(const float* p) {
    return *reinterpret_cast<const ull*>(p);
}
__device__ __forceinline__ void sts2(float* p, float x, float y) {
    *reinterpret_cast<float2*>(p) = make_float2(x, y);
}
__device__ __forceinline__ uint32 f2tf(float x) {
    uint32 u; asm("cvt.rna.tf32.f32 %0, %1;" : "=r"(u) : "f"(x)); return u;
}
__device__ __forceinline__ void mma8(float& d0, float& d1, float& d2, float& d3,
                                     uint32 a0, uint32 a1, uint32 a2, uint32 a3,
                                     uint32 b0, uint32 b1) {
    asm volatile(
        "mma.sync.aligned.m16n8k8.row.col.f32.tf32.tf32.f32 "
        "{%0,%1,%2,%3},{%4,%5,%6,%7},{%8,%9},{%0,%1,%2,%3};"
        : "+f"(d0), "+f"(d1), "+f"(d2), "+f"(d3)
        : "r"(a0), "r"(a1), "r"(a2), "r"(a3), "r"(b0), "r"(b1));
}

__global__ void k_init(const float* __restrict__ emb_elec) {
    const int total = NB * NE * ED;
    for (int idx = blockIdx.x * blockDim.x + threadIdx.x; idx < total;
         idx += gridDim.x * blockDim.x) {
        int d = idx % ED, i = (idx / ED) % NE;
        g_xs[idx] = emb_elec[i * ED + d];
    }
}

// ---------------------------------------------------------------------------
// One-time fragment prepack: block l handles layer l.
// ---------------------------------------------------------------------------
__global__ void k_prepack(const float* __restrict__ kw1,
                          const float* __restrict__ kw2,
                          const float* __restrict__ ow1,
                          const float* __restrict__ ow2) {
    const int l = blockIdx.x, tid = threadIdx.x;
    const float* w1 = kw1 + (size_t)l * BASIS * HK;
    const float* w2 = kw2 + (size_t)l * HK * KD;
    const float* W1 = ow1 + (size_t)l * KD * HO;
    const float* W2 = ow2 + (size_t)l * HO * ED;

    for (int it = tid; it < 6 * 4 * 32; it += 256) {
        int lane_ = it & 31;
        int kt = (it >> 5) & 3;
        int nt = it >> 7;
        int g_ = lane_ >> 2, t_ = lane_ & 3;
        int n  = nt * 8 + g_;
        int k0 = kt * 8 + t_;
        bool ok = (n < HK);
        g_B1f[l][it] = make_uint2(f2tf(ok ? w1[k0 * HK + n] : 0.f),
                                  f2tf(ok ? w1[(k0 + 4) * HK + n] : 0.f));
    }
    for (int it = tid; it < 8 * 6 * 32; it += 256) {
        int lane_ = it & 31;
        int kt = (it >> 5) % 6;
        int nt = it / 192;
        int g_ = lane_ >> 2, t_ = lane_ & 3;
        int n  = nt * 8 + g_;
        int k0 = kt * 8 + t_, k1 = k0 + 4;
        g_B2f[l][it] = make_uint2(f2tf((k0 < HK) ? w2[k0 * KD + n] : 0.f),
                                  f2tf((k1 < HK) ? w2[k1 * KD + n] : 0.f));
    }
    for (int it = tid; it < 12 * 8 * 32; it += 256) {
        int lane_ = it & 31;
        int kt = (it >> 5) & 7;
        int nt = it >> 8;
        int g_ = lane_ >> 2, t_ = lane_ & 3;
        int n  = nt * 8 + g_;
        int k0 = kt * 8 + t_;
        bool ok = (n < HO);
        g_B1o[l][it] = make_uint2(f2tf(ok ? W1[k0 * HO + n] : 0.f),
                                  f2tf(ok ? W1[(k0 + 4) * HO + n] : 0.f));
    }
    for (int it = tid; it < 16 * 12 * 32; it += 256) {
        int lane_ = it & 31;
        int kt = (it >> 5) % 12;
        int nt = it / 384;
        int g_ = lane_ >> 2, t_ = lane_ & 3;
        int n  = nt * 8 + g_;
        int k0 = kt * 8 + t_;
        g_B2o[l][it] = make_uint2(f2tf((k0 < HO) ? W2[k0 * ED + n] : 0.f),
                                  f2tf((k0 + 4 < HO) ? W2[(k0 + 4) * ED + n] : 0.f));
    }
}

// ---------------------------------------------------------------------------
// k_layer = msg (pair MLP, MMA) + fused out MLP (MMA).
// smem (floats):
//   zsv   [0,3456)       zs[j][c], j 0..47 (38..47 zero), stride 72
//   smsg  [3456,5632)    32 rows x stride 68 (rows>=30 zero)
//   scratch [5632,17664) (12032 floats)
//     phase1: eiwv 8192 @scratch | xs2 3840 @scratch+8192
//     phase2: B1f uint2[768] (1536 f) @scratch
//             B2f uint2[1536] (3072 f) @scratch+1536
//     out:    Hs 32x100 (3200 f) @scratch
//   sb1 [17664,17712) | sb2 [17712,17776) | sb1o [17776,17872) | sb2o [17872,18000)
// ---------------------------------------------------------------------------
#define MS_TOTAL_F 18000
#define MS_BYTES   (MS_TOTAL_F * 4)

__global__ void __launch_bounds__(256, 3) k_layer(
        const float* __restrict__ dists,
        const float* __restrict__ emb_nuc,
        const float* __restrict__ eiw,
        const float* __restrict__ kb1,
        const float* __restrict__ kb2,
        const float* __restrict__ ob1,
        const float* __restrict__ ob2,
        int l, float* __restrict__ xs_out) {
    extern __shared__ float sm[];
    float*  zsv     = sm;
    float*  smsg    = sm + 3456;
    float*  scratch = sm + 5632;
    float*  eiwv    = scratch;
    float*  xs2     = scratch + 8192;
    uint2*  B1f     = reinterpret_cast<uint2*>(scratch);
    uint2*  B2f     = reinterpret_cast<uint2*>(scratch + 1536);
    uint32* Hs      = reinterpret_cast<uint32*>(scratch);
    float*  sb1     = sm + 17664;
    float*  sb2     = sm + 17712;
    float*  sb1o    = sm + 17776;
    float*  sb2o    = sm + 17872;

    const int b = blockIdx.x, tid = threadIdx.x;
    const int w = tid >> 5, lane = tid & 31;
    const int g = lane >> 2, t = lane & 3;
    const int odd = t & 1;
    const int src0 = (lane & ~3) | (t >> 1);   // quad-local col source
    const int src1 = src0 + 2;

    // ---- phase 1a: stage eiw + xs, nuclear zs, pads, biases ----
    {
        const float* W = eiw + (size_t)l * ED * KD;
        for (int it = tid; it < ED * 32; it += 256) {
            int q = it >> 5, c = it & 31;
            sts2(eiwv + 2 * it, W[q * KD + c], W[q * KD + c + 32]);
        }
        const float* xsb = g_xs + (size_t)b * NE * ED;
        for (int it = tid; it < 15 * ED; it += 256) {
            int p = it >> 7, q = it & 127;
            sts2(xs2 + 2 * it, xsb[(2 * p) * ED + q], xsb[(2 * p + 1) * ED + q]);
        }
        for (int idx = tid; idx < NN * KD; idx += 256) {
            int n = idx >> 6, c = idx & 63;
            zsv[(NE + n) * 72 + c] = emb_nuc[n * KD + c];
        }
        for (int idx = tid; idx < 10 * 64; idx += 256) {
            int r = idx >> 6, c = idx & 63;
            zsv[(38 + r) * 72 + c] = 0.f;
        }
        for (int idx = tid; idx < 2 * 68; idx += 256)
            smsg[30 * 68 + idx] = 0.f;
        if (tid < 48)  sb1[tid]  = (tid < HK) ? kb1[l * HK + tid] : 0.f;
        if (tid < 64)  sb2[tid]  = kb2[l * KD + tid];
        if (tid < 96)  sb1o[tid] = (tid < HO) ? ob1[l * HO + tid] : 0.f;
        if (tid < 128) sb2o[tid] = ob2[l * ED + tid];
    }
    __syncthreads();

    // ---- phase 1b: electron zs = xs @ eiw (f32x2 over electron pairs) ----
    for (int p = w; p < 15; p += 8) {
        ull acc0 = 0ull, acc1 = 0ull;
        const float* xrow = xs2 + p * 256;
        #pragma unroll 8
        for (int q = 0; q < ED; ++q) {
            ull x2 = ldsu64(xrow + 2 * q);
            float2 wf = unpack2(ldsu64(eiwv + (q * 32 + lane) * 2));
            acc0 = ffma2(x2, dup2(wf.x), acc0);
            acc1 = ffma2(x2, dup2(wf.y), acc1);
        }
        float2 a0 = unpack2(acc0), a1 = unpack2(acc1);
        zsv[(2 * p) * 72 + lane]          = a0.x;
        zsv[(2 * p + 1) * 72 + lane]      = a0.y;
        zsv[(2 * p) * 72 + lane + 32]     = a1.x;
        zsv[(2 * p + 1) * 72 + lane + 32] = a1.y;
    }
    __syncthreads();

    // ---- phase 2a: copy prepacked msg B-fragments into smem ----
    {
        const uint4* s1 = reinterpret_cast<const uint4*>(g_B1f[l]);
        uint4* d1 = reinterpret_cast<uint4*>(B1f);
        for (int it = tid; it < 384; it += 256) d1[it] = s1[it];
        const uint4* s2 = reinterpret_cast<const uint4*>(g_B2f[l]);
        uint4* d2 = reinterpret_cast<uint4*>(B2f);
        for (int it = tid; it < 768; it += 256) d2[it] = s2[it];
    }
    __syncthreads();

    // ---- main loop: pair MLP + j-sum -> smsg ----
    for (int i = w; i < NE; i += 8) {
        const float* dbase = dists + ((size_t)(b * NE + i)) * NA * BASIS;
        float macc[16];
        #pragma unroll
        for (int r = 0; r < 16; ++r) macc[r] = 0.f;

        #pragma unroll
        for (int mt = 0; mt < 3; ++mt) {
            const int j0 = mt * 16 + g, j1 = j0 + 8;

            uint32 A1[4][4];
            #pragma unroll
            for (int kt = 0; kt < 4; ++kt) {
                int k0 = kt * 8 + t;
                float a0 = (j0 < NA) ? __ldg(dbase + j0 * BASIS + k0) : 0.f;
                float a1 = (j1 < NA) ? __ldg(dbase + j1 * BASIS + k0) : 0.f;
                float a2 = (j0 < NA) ? __ldg(dbase + j0 * BASIS + k0 + 4) : 0.f;
                float a3 = (j1 < NA) ? __ldg(dbase + j1 * BASIS + k0 + 4) : 0.f;
                A1[kt][0] = f2tf(a0); A1[kt][1] = f2tf(a1);
                A1[kt][2] = f2tf(a2); A1[kt][3] = f2tf(a3);
            }

            // GEMM1 + ssp; D-fragment -> A2 fragment via quad shuffles
            uint32 A2[6][4];
            #pragma unroll
            for (int nt = 0; nt < 6; ++nt) {
                float2 bb = *reinterpret_cast<const float2*>(sb1 + nt * 8 + 2 * t);
                float d0 = bb.x, d1 = bb.y, d2 = bb.x, d3 = bb.y;
                const uint2* bp = B1f + nt * 128 + lane;
                #pragma unroll
                for (int kt = 0; kt < 4; ++kt) {
                    uint2 bf = bp[kt * 32];
                    mma8(d0, d1, d2, d3,
                         A1[kt][0], A1[kt][1], A1[kt][2], A1[kt][3],
                         bf.x, bf.y);
                }
                uint32 v0 = f2tf(ssp(d0)), v1 = f2tf(ssp(d1));
                uint32 v2 = f2tf(ssp(d2)), v3 = f2tf(ssp(d3));
                // H[g][8nt+2t],H[g][8nt+2t+1] = v0,v1 ; rows g+8 = v2,v3
                uint32 x00 = __shfl_sync(0xffffffffu, v0, src0);
                uint32 x01 = __shfl_sync(0xffffffffu, v1, src0);
                uint32 x10 = __shfl_sync(0xffffffffu, v0, src1);
                uint32 x11 = __shfl_sync(0xffffffffu, v1, src1);
                uint32 x20 = __shfl_sync(0xffffffffu, v2, src0);
                uint32 x21 = __shfl_sync(0xffffffffu, v3, src0);
                uint32 x30 = __shfl_sync(0xffffffffu, v2, src1);
                uint32 x31 = __shfl_sync(0xffffffffu, v3, src1);
                A2[nt][0] = odd ? x01 : x00;   // H[g][8nt+t]
                A2[nt][2] = odd ? x11 : x10;   // H[g][8nt+t+4]
                A2[nt][1] = odd ? x21 : x20;   // H[g+8][8nt+t]
                A2[nt][3] = odd ? x31 : x30;   // H[g+8][8nt+t+4]
            }

            const float pm0 = (j0 != i) ? 1.f : 0.f;
            const float pm1 = (j1 != i) ? 1.f : 0.f;

            #pragma unroll
            for (int nt = 0; nt < 8; ++nt) {
                float2 bb = *reinterpret_cast<const float2*>(sb2 + nt * 8 + 2 * t);
                float d0 = bb.x, d1 = bb.y, d2 = bb.x, d3 = bb.y;
                const uint2* bp = B2f + nt * 192 + lane;
                #pragma unroll
                for (int kt = 0; kt < 6; ++kt) {
                    uint2 bf = bp[kt * 32];
                    mma8(d0, d1, d2, d3,
                         A2[kt][0], A2[kt][1], A2[kt][2], A2[kt][3],
                         bf.x, bf.y);
                }
                float2 z0 = *reinterpret_cast<const float2*>(zsv + j0 * 72 + nt * 8 + 2 * t);
                float2 z1 = *reinterpret_cast<const float2*>(zsv + j1 * 72 + nt * 8 + 2 * t);
                macc[2 * nt]     += pm0 * d0 * z0.x + pm1 * d2 * z1.x;
                macc[2 * nt + 1] += pm0 * d1 * z0.y + pm1 * d3 * z1.y;
            }
        }

        #pragma unroll
        for (int r = 0; r < 16; ++r) {
            macc[r] += __shfl_xor_sync(0xffffffffu, macc[r], 4);
            macc[r] += __shfl_xor_sync(0xffffffffu, macc[r], 8);
            macc[r] += __shfl_xor_sync(0xffffffffu, macc[r], 16);
        }
        if (g == 0) {
            #pragma unroll
            for (int nt = 0; nt < 8; ++nt)
                sts2(smsg + i * 68 + nt * 8 + 2 * t, macc[2 * nt], macc[2 * nt + 1]);
        }
    }
    __syncthreads();   // smsg complete; scratch (B1f/B2f) now dead

    // ---- out GEMM1: Hs = ssp(msg @ W1 + b1); warp covers nt = w, w+8 ----
    #pragma unroll
    for (int mt = 0; mt < 2; ++mt) {
        int r0 = (mt * 16 + g) * 68, r1 = (mt * 16 + g + 8) * 68;
        #pragma unroll
        for (int rep = 0; rep < 2; ++rep) {
            int nt = w + 8 * rep;
            if (nt < 12) {
                float2 bb = *reinterpret_cast<const float2*>(sb1o + nt * 8 + 2 * t);
                float d0 = bb.x, d1 = bb.y, d2 = bb.x, d3 = bb.y;
                const uint2* bp = g_B1o[l] + nt * 256 + lane;
                #pragma unroll
                for (int kt = 0; kt < 8; ++kt) {
                    int c = kt * 8 + t;
                    uint32 a0 = f2tf(smsg[r0 + c]);
                    uint32 a1 = f2tf(smsg[r1 + c]);
                    uint32 a2 = f2tf(smsg[r0 + c + 4]);
                    uint32 a3 = f2tf(smsg[r1 + c + 4]);
                    uint2 bf = __ldg(bp + kt * 32);
                    mma8(d0, d1, d2, d3, a0, a1, a2, a3, bf.x, bf.y);
                }
                int c = nt * 8 + 2 * t;
                *reinterpret_cast<uint2*>(Hs + (mt * 16 + g) * 100 + c) =
                    make_uint2(f2tf(ssp(d0)), f2tf(ssp(d1)));
                *reinterpret_cast<uint2*>(Hs + (mt * 16 + g + 8) * 100 + c) =
                    make_uint2(f2tf(ssp(d2)), f2tf(ssp(d3)));
            }
        }
    }
    __syncthreads();

    // ---- out GEMM2 + residual: xs_out = xs + Hs @ W2 + b2; nt = 2w, 2w+1 ----
    #pragma unroll
    for (int mt = 0; mt < 2; ++mt) {
        int r0 = (mt * 16 + g) * 100, r1 = (mt * 16 + g + 8) * 100;
        int e0 = mt * 16 + g, e1 = e0 + 8;
        #pragma unroll
        for (int idx = 0; idx < 2; ++idx) {
            int nt = 2 * w + idx;
            float2 bb = *reinterpret_cast<const float2*>(sb2o + nt * 8 + 2 * t);
            float d0 = bb.x, d1 = bb.y, d2 = bb.x, d3 = bb.y;
            const uint2* bp = g_B2o[l] + nt * 384 + lane;
            #pragma unroll
            for (int kt = 0; kt < 12; ++kt) {
                int c = kt * 8 + t;
                uint2 bf = __ldg(bp + kt * 32);
                mma8(d0, d1, d2, d3,
                     Hs[r0 + c], Hs[r1 + c], Hs[r0 + c + 4], Hs[r1 + c + 4],
                     bf.x, bf.y);
            }
            int c = nt * 8 + 2 * t;
            if (e0 < NE) {
                size_t o = ((size_t)(b * NE + e0)) * ED + c;
                float2 xv = *reinterpret_cast<const float2*>(g_xs + o);
                *reinterpret_cast<float2*>(xs_out + o) =
                    make_float2(xv.x + d0, xv.y + d1);
            }
            if (e1 < NE) {
                size_t o = ((size_t)(b * NE + e1)) * ED + c;
                float2 xv = *reinterpret_cast<const float2*>(g_xs + o);
                *reinterpret_cast<float2*>(xs_out + o) =
                    make_float2(xv.x + d2, xv.y + d3);
            }
        }
    }
}

// ---------------------------------------------------------------------------
extern "C" void kernel_launch(void* const* d_in, const int* in_sizes, int n_in,
                              void* d_out, int out_size) {
    const float* dists    = (const float*)d_in[0];
    const float* emb_elec = (const float*)d_in[1];
    const float* emb_nuc  = (const float*)d_in[2];
    const float* kw1      = (const float*)d_in[3];
    const float* kb1      = (const float*)d_in[4];
    const float* kw2      = (const float*)d_in[5];
    const float* kb2      = (const float*)d_in[6];
    const float* eiw      = (const float*)d_in[7];
    const float* ow1      = (const float*)d_in[8];
    const float* ob1      = (const float*)d_in[9];
    const float* ow2      = (const float*)d_in[10];
    const float* ob2      = (const float*)d_in[11];
    float* out = (float*)d_out;

    static int configured = 0;
    if (!configured) {
        cudaFuncSetAttribute(k_layer, cudaFuncAttributeMaxDynamicSharedMemorySize, MS_BYTES);
        configured = 1;
    }
    void* xsptr = nullptr;
    cudaGetSymbolAddress(&xsptr, g_xs);

    k_init<<<4096, 256>>>(emb_elec);
    k_prepack<<<NL, 256>>>(kw1, kw2, ow1, ow2);
    for (int l = 0; l < NL; ++l) {
        float* xs_out = (l == NL - 1) ? out : (float*)xsptr;
        k_layer<<<NB, 256, MS_BYTES>>>(dists, emb_nuc, eiw, kb1, kb2, ob1, ob2,
                                       l, xs_out);
    }
}

// round 12
// speedup vs baseline: 2.2922x; 2.2922x over previous
#include <cuda_runtime.h>

#define NB    2048
#define NE    30
#define NA    38
#define NN    8
#define BASIS 32
#define KD    64
#define ED    128
#define HK    45
#define HO    91
#define NL    3

typedef unsigned long long ull;
typedef unsigned int uint32;

__device__ float g_xs [NB * NE * ED];

// Prepacked tf32 B-fragments, kt-PAIR packed (uint4 = two mma B operands).
__device__ uint4 g_B1f[NL][6 * 2 * 32];     // msg w1  [nt6][kt2:2][lane]
__device__ uint4 g_B2f[NL][8 * 3 * 32];     // msg w2  [nt8][kt2:3][lane]
__device__ uint4 g_B1o[NL][12 * 4 * 32];    // out W1  [nt12][kt2:4][lane]
__device__ uint4 g_B2o[NL][16 * 6 * 32];    // out W2  [nt16][kt2:6][lane]

__device__ __forceinline__ float ssp(float x) {
    float t = __expf(-fabsf(x));
    return fmaxf(x, 0.f) + __logf(1.f + t) - 0.69314718055994530942f;
}
__device__ __forceinline__ ull ffma2(ull a, ull b, ull c) {
    ull d; asm("fma.rn.f32x2 %0, %1, %2, %3;" : "=l"(d) : "l"(a), "l"(b), "l"(c));
    return d;
}
__device__ __forceinline__ ull pack2(float x, float y) {
    ull r; asm("mov.b64 %0, {%1, %2};" : "=l"(r) : "f"(x), "f"(y)); return r;
}
__device__ __forceinline__ ull dup2(float x) { return pack2(x, x); }
__device__ __forceinline__ float2 unpack2(ull v) {
    float2 r; asm("mov.b64 {%0, %1}, %2;" : "=f"(r.x), "=f"(r.y) : "l"(v)); return r;
}
__device__ __forceinline__ ull ldsu64(const float* p) {
    return *reinterpret_cast<const ull*>(p);
}
__device__ __forceinline__ void sts2(float* p, float x, float y) {
    *reinterpret_cast<float2*>(p) = make_float2(x, y);
}
__device__ __forceinline__ uint32 f2tf(float x) {
    uint32 u; asm("cvt.rna.tf32.f32 %0, %1;" : "=r"(u) : "f"(x)); return u;
}
__device__ __forceinline__ void mma8(float& d0, float& d1, float& d2, float& d3,
                                     uint32 a0, uint32 a1, uint32 a2, uint32 a3,
                                     uint32 b0, uint32 b1) {
    asm volatile(
        "mma.sync.aligned.m16n8k8.row.col.f32.tf32.tf32.f32 "
        "{%0,%1,%2,%3},{%4,%5,%6,%7},{%8,%9},{%0,%1,%2,%3};"
        : "+f"(d0), "+f"(d1), "+f"(d2), "+f"(d3)
        : "r"(a0), "r"(a1), "r"(a2), "r"(a3), "r"(b0), "r"(b1));
}

__global__ void k_init(const float* __restrict__ emb_elec) {
    const int total = NB * NE * ED;
    for (int idx = blockIdx.x * blockDim.x + threadIdx.x; idx < total;
         idx += gridDim.x * blockDim.x) {
        int d = idx % ED, i = (idx / ED) % NE;
        g_xs[idx] = emb_elec[i * ED + d];
    }
}

// ---------------------------------------------------------------------------
// One-time fragment prepack (kt-pair uint4 layout): block l handles layer l.
// uint4 = { b0(kt=2*kt2), b1(kt=2*kt2), b0(kt=2*kt2+1), b1(kt=2*kt2+1) }
//       = rows { ka, ka+4, ka+8, ka+12 }, ka = kt2*16 + t
// ---------------------------------------------------------------------------
__global__ void k_prepack(const float* __restrict__ kw1,
                          const float* __restrict__ kw2,
                          const float* __restrict__ ow1,
                          const float* __restrict__ ow2) {
    const int l = blockIdx.x, tid = threadIdx.x;
    const float* w1 = kw1 + (size_t)l * BASIS * HK;
    const float* w2 = kw2 + (size_t)l * HK * KD;
    const float* W1 = ow1 + (size_t)l * KD * HO;
    const float* W2 = ow2 + (size_t)l * HO * ED;

    for (int it = tid; it < 6 * 2 * 32; it += 256) {
        int lane_ = it & 31;
        int kt2 = (it >> 5) & 1;
        int nt  = it >> 6;
        int g_ = lane_ >> 2, t_ = lane_ & 3;
        int n  = nt * 8 + g_;
        int ka = kt2 * 16 + t_;
        bool ok = (n < HK);
        g_B1f[l][it] = make_uint4(f2tf(ok ? w1[ka * HK + n] : 0.f),
                                  f2tf(ok ? w1[(ka + 4) * HK + n] : 0.f),
                                  f2tf(ok ? w1[(ka + 8) * HK + n] : 0.f),
                                  f2tf(ok ? w1[(ka + 12) * HK + n] : 0.f));
    }
    for (int it = tid; it < 8 * 3 * 32; it += 256) {
        int lane_ = it & 31;
        int kt2 = (it >> 5) % 3;
        int nt  = it / 96;
        int g_ = lane_ >> 2, t_ = lane_ & 3;
        int n  = nt * 8 + g_;
        int ka = kt2 * 16 + t_;
        g_B2f[l][it] = make_uint4(
            f2tf((ka      < HK) ? w2[ka * KD + n] : 0.f),
            f2tf((ka + 4  < HK) ? w2[(ka + 4) * KD + n] : 0.f),
            f2tf((ka + 8  < HK) ? w2[(ka + 8) * KD + n] : 0.f),
            f2tf((ka + 12 < HK) ? w2[(ka + 12) * KD + n] : 0.f));
    }
    for (int it = tid; it < 12 * 4 * 32; it += 256) {
        int lane_ = it & 31;
        int kt2 = (it >> 5) & 3;
        int nt  = it >> 7;
        int g_ = lane_ >> 2, t_ = lane_ & 3;
        int n  = nt * 8 + g_;
        int ka = kt2 * 16 + t_;
        bool ok = (n < HO);
        g_B1o[l][it] = make_uint4(f2tf(ok ? W1[ka * HO + n] : 0.f),
                                  f2tf(ok ? W1[(ka + 4) * HO + n] : 0.f),
                                  f2tf(ok ? W1[(ka + 8) * HO + n] : 0.f),
                                  f2tf(ok ? W1[(ka + 12) * HO + n] : 0.f));
    }
    for (int it = tid; it < 16 * 6 * 32; it += 256) {
        int lane_ = it & 31;
        int kt2 = (it >> 5) % 6;
        int nt  = it / 192;
        int g_ = lane_ >> 2, t_ = lane_ & 3;
        int n  = nt * 8 + g_;
        int ka = kt2 * 16 + t_;
        g_B2o[l][it] = make_uint4(
            f2tf((ka      < HO) ? W2[ka * ED + n] : 0.f),
            f2tf((ka + 4  < HO) ? W2[(ka + 4) * ED + n] : 0.f),
            f2tf((ka + 8  < HO) ? W2[(ka + 8) * ED + n] : 0.f),
            f2tf((ka + 12 < HO) ? W2[(ka + 12) * ED + n] : 0.f));
    }
}

// ---------------------------------------------------------------------------
// k_layer = msg (pair MLP, MMA) + fused out MLP (MMA).  Same smem map as R9.
// ---------------------------------------------------------------------------
#define MS_TOTAL_F 18000
#define MS_BYTES   (MS_TOTAL_F * 4)

__global__ void __launch_bounds__(256, 3) k_layer(
        const float* __restrict__ dists,
        const float* __restrict__ emb_nuc,
        const float* __restrict__ eiw,
        const float* __restrict__ kb1,
        const float* __restrict__ kb2,
        const float* __restrict__ ob1,
        const float* __restrict__ ob2,
        int l, float* __restrict__ xs_out) {
    extern __shared__ float sm[];
    float*  zsv     = sm;
    float*  smsg    = sm + 3456;
    float*  scratch = sm + 5632;
    float*  eiwv    = scratch;
    float*  xs2     = scratch + 8192;
    uint4*  B1f     = reinterpret_cast<uint4*>(scratch);           // 384 uint4
    uint4*  B2f     = reinterpret_cast<uint4*>(scratch + 1536);    // 768 uint4
    uint32* Hall    = reinterpret_cast<uint32*>(scratch + 4608);
    uint32* Hs      = reinterpret_cast<uint32*>(scratch);
    float*  sb1     = sm + 17664;
    float*  sb2     = sm + 17712;
    float*  sb1o    = sm + 17776;
    float*  sb2o    = sm + 17872;

    const int b = blockIdx.x, tid = threadIdx.x;
    const int w = tid >> 5, lane = tid & 31;
    const int g = lane >> 2, t = lane & 3;

    // ---- phase 1a: stage eiw + xs, nuclear zs, pads, biases ----
    {
        const float* W = eiw + (size_t)l * ED * KD;
        for (int it = tid; it < ED * 32; it += 256) {
            int q = it >> 5, c = it & 31;
            sts2(eiwv + 2 * it, W[q * KD + c], W[q * KD + c + 32]);
        }
        const float* xsb = g_xs + (size_t)b * NE * ED;
        for (int it = tid; it < 15 * ED; it += 256) {
            int p = it >> 7, q = it & 127;
            sts2(xs2 + 2 * it, xsb[(2 * p) * ED + q], xsb[(2 * p + 1) * ED + q]);
        }
        for (int idx = tid; idx < NN * KD; idx += 256) {
            int n = idx >> 6, c = idx & 63;
            zsv[(NE + n) * 72 + c] = emb_nuc[n * KD + c];
        }
        for (int idx = tid; idx < 10 * 64; idx += 256) {
            int r = idx >> 6, c = idx & 63;
            zsv[(38 + r) * 72 + c] = 0.f;
        }
        for (int idx = tid; idx < 2 * 68; idx += 256)
            smsg[30 * 68 + idx] = 0.f;
        if (tid < 48)  sb1[tid]  = (tid < HK) ? kb1[l * HK + tid] : 0.f;
        if (tid < 64)  sb2[tid]  = kb2[l * KD + tid];
        if (tid < 96)  sb1o[tid] = (tid < HO) ? ob1[l * HO + tid] : 0.f;
        if (tid < 128) sb2o[tid] = ob2[l * ED + tid];
    }
    __syncthreads();

    // ---- phase 1b: electron zs = xs @ eiw (f32x2 over electron pairs) ----
    for (int p = w; p < 15; p += 8) {
        ull acc0 = 0ull, acc1 = 0ull;
        const float* xrow = xs2 + p * 256;
        #pragma unroll 8
        for (int q = 0; q < ED; ++q) {
            ull x2 = ldsu64(xrow + 2 * q);
            float2 wf = unpack2(ldsu64(eiwv + (q * 32 + lane) * 2));
            acc0 = ffma2(x2, dup2(wf.x), acc0);
            acc1 = ffma2(x2, dup2(wf.y), acc1);
        }
        float2 a0 = unpack2(acc0), a1 = unpack2(acc1);
        zsv[(2 * p) * 72 + lane]          = a0.x;
        zsv[(2 * p + 1) * 72 + lane]      = a0.y;
        zsv[(2 * p) * 72 + lane + 32]     = a1.x;
        zsv[(2 * p + 1) * 72 + lane + 32] = a1.y;
    }
    __syncthreads();

    // ---- phase 2a: copy prepacked msg B-fragments into smem (uint4) ----
    {
        const uint4* s1 = g_B1f[l];
        for (int it = tid; it < 384; it += 256) B1f[it] = s1[it];
        const uint4* s2 = g_B2f[l];
        for (int it = tid; it < 768; it += 256) B2f[it] = s2[it];
    }
    __syncthreads();

    uint32* Hw = Hall + w * 832;

    // ---- main loop: pair MLP + j-sum -> smsg ----
    for (int i = w; i < NE; i += 8) {
        const float* dbase = dists + ((size_t)(b * NE + i)) * NA * BASIS;
        float macc[16];
        #pragma unroll
        for (int r = 0; r < 16; ++r) macc[r] = 0.f;

        #pragma unroll
        for (int mt = 0; mt < 3; ++mt) {
            const int j0 = mt * 16 + g, j1 = j0 + 8;

            uint32 A1[4][4];
            #pragma unroll
            for (int kt = 0; kt < 4; ++kt) {
                int k0 = kt * 8 + t;
                float a0 = (j0 < NA) ? __ldg(dbase + j0 * BASIS + k0) : 0.f;
                float a1 = (j1 < NA) ? __ldg(dbase + j1 * BASIS + k0) : 0.f;
                float a2 = (j0 < NA) ? __ldg(dbase + j0 * BASIS + k0 + 4) : 0.f;
                float a3 = (j1 < NA) ? __ldg(dbase + j1 * BASIS + k0 + 4) : 0.f;
                A1[kt][0] = f2tf(a0); A1[kt][1] = f2tf(a1);
                A1[kt][2] = f2tf(a2); A1[kt][3] = f2tf(a3);
            }

            #pragma unroll
            for (int nt = 0; nt < 6; ++nt) {
                float2 bb = *reinterpret_cast<const float2*>(sb1 + nt * 8 + 2 * t);
                float d0 = bb.x, d1 = bb.y, d2 = bb.x, d3 = bb.y;
                const uint4* bp = B1f + nt * 64 + lane;
                #pragma unroll
                for (int kt2 = 0; kt2 < 2; ++kt2) {
                    uint4 bf = bp[kt2 * 32];
                    mma8(d0, d1, d2, d3,
                         A1[2 * kt2][0], A1[2 * kt2][1], A1[2 * kt2][2], A1[2 * kt2][3],
                         bf.x, bf.y);
                    mma8(d0, d1, d2, d3,
                         A1[2 * kt2 + 1][0], A1[2 * kt2 + 1][1], A1[2 * kt2 + 1][2], A1[2 * kt2 + 1][3],
                         bf.z, bf.w);
                }
                uint2 lo = make_uint2(f2tf(ssp(d0)), f2tf(ssp(d1)));
                uint2 hi = make_uint2(f2tf(ssp(d2)), f2tf(ssp(d3)));
                *reinterpret_cast<uint2*>(Hw + g * 52 + nt * 8 + 2 * t)       = lo;
                *reinterpret_cast<uint2*>(Hw + (g + 8) * 52 + nt * 8 + 2 * t) = hi;
            }
            __syncwarp();

            uint32 A2[6][4];
            #pragma unroll
            for (int kt = 0; kt < 6; ++kt) {
                A2[kt][0] = Hw[g * 52 + kt * 8 + t];
                A2[kt][1] = Hw[(g + 8) * 52 + kt * 8 + t];
                A2[kt][2] = Hw[g * 52 + kt * 8 + t + 4];
                A2[kt][3] = Hw[(g + 8) * 52 + kt * 8 + t + 4];
            }
            const float pm0 = (j0 != i) ? 1.f : 0.f;
            const float pm1 = (j1 != i) ? 1.f : 0.f;

            #pragma unroll
            for (int nt = 0; nt < 8; ++nt) {
                float2 bb = *reinterpret_cast<const float2*>(sb2 + nt * 8 + 2 * t);
                float d0 = bb.x, d1 = bb.y, d2 = bb.x, d3 = bb.y;
                const uint4* bp = B2f + nt * 96 + lane;
                #pragma unroll
                for (int kt2 = 0; kt2 < 3; ++kt2) {
                    uint4 bf = bp[kt2 * 32];
                    mma8(d0, d1, d2, d3,
                         A2[2 * kt2][0], A2[2 * kt2][1], A2[2 * kt2][2], A2[2 * kt2][3],
                         bf.x, bf.y);
                    mma8(d0, d1, d2, d3,
                         A2[2 * kt2 + 1][0], A2[2 * kt2 + 1][1], A2[2 * kt2 + 1][2], A2[2 * kt2 + 1][3],
                         bf.z, bf.w);
                }
                float2 z0 = *reinterpret_cast<const float2*>(zsv + j0 * 72 + nt * 8 + 2 * t);
                float2 z1 = *reinterpret_cast<const float2*>(zsv + j1 * 72 + nt * 8 + 2 * t);
                macc[2 * nt]     += pm0 * d0 * z0.x + pm1 * d2 * z1.x;
                macc[2 * nt + 1] += pm0 * d1 * z0.y + pm1 * d3 * z1.y;
            }
            __syncwarp();
        }

        #pragma unroll
        for (int r = 0; r < 16; ++r) {
            macc[r] += __shfl_xor_sync(0xffffffffu, macc[r], 4);
            macc[r] += __shfl_xor_sync(0xffffffffu, macc[r], 8);
            macc[r] += __shfl_xor_sync(0xffffffffu, macc[r], 16);
        }
        if (g == 0) {
            #pragma unroll
            for (int nt = 0; nt < 8; ++nt)
                sts2(smsg + i * 68 + nt * 8 + 2 * t, macc[2 * nt], macc[2 * nt + 1]);
        }
    }
    __syncthreads();   // smsg complete; scratch (B1f/B2f/H) now dead

    // ---- out GEMM1: Hs = ssp(msg @ W1 + b1); warp covers nt = w, w+8 ----
    #pragma unroll
    for (int mt = 0; mt < 2; ++mt) {
        int r0 = (mt * 16 + g) * 68, r1 = (mt * 16 + g + 8) * 68;
        #pragma unroll
        for (int rep = 0; rep < 2; ++rep) {
            int nt = w + 8 * rep;
            if (nt < 12) {
                float2 bb = *reinterpret_cast<const float2*>(sb1o + nt * 8 + 2 * t);
                float d0 = bb.x, d1 = bb.y, d2 = bb.x, d3 = bb.y;
                const uint4* bp = g_B1o[l] + nt * 128 + lane;
                #pragma unroll
                for (int kt2 = 0; kt2 < 4; ++kt2) {
                    uint4 bf = __ldg(bp + kt2 * 32);
                    #pragma unroll
                    for (int h = 0; h < 2; ++h) {
                        int kt = 2 * kt2 + h;
                        int c = kt * 8 + t;
                        uint32 a0 = f2tf(smsg[r0 + c]);
                        uint32 a1 = f2tf(smsg[r1 + c]);
                        uint32 a2 = f2tf(smsg[r0 + c + 4]);
                        uint32 a3 = f2tf(smsg[r1 + c + 4]);
                        mma8(d0, d1, d2, d3, a0, a1, a2, a3,
                             h ? bf.z : bf.x, h ? bf.w : bf.y);
                    }
                }
                int c = nt * 8 + 2 * t;
                *reinterpret_cast<uint2*>(Hs + (mt * 16 + g) * 100 + c) =
                    make_uint2(f2tf(ssp(d0)), f2tf(ssp(d1)));
                *reinterpret_cast<uint2*>(Hs + (mt * 16 + g + 8) * 100 + c) =
                    make_uint2(f2tf(ssp(d2)), f2tf(ssp(d3)));
            }
        }
    }
    __syncthreads();

    // ---- out GEMM2 + residual: xs_out = xs + Hs @ W2 + b2; nt = 2w, 2w+1 ----
    #pragma unroll
    for (int mt = 0; mt < 2; ++mt) {
        int r0 = (mt * 16 + g) * 100, r1 = (mt * 16 + g + 8) * 100;
        int e0 = mt * 16 + g, e1 = e0 + 8;
        #pragma unroll
        for (int idx = 0; idx < 2; ++idx) {
            int nt = 2 * w + idx;
            float2 bb = *reinterpret_cast<const float2*>(sb2o + nt * 8 + 2 * t);
            float d0 = bb.x, d1 = bb.y, d2 = bb.x, d3 = bb.y;
            const uint4* bp = g_B2o[l] + nt * 192 + lane;
            #pragma unroll
            for (int kt2 = 0; kt2 < 6; ++kt2) {
                uint4 bf = __ldg(bp + kt2 * 32);
                #pragma unroll
                for (int h = 0; h < 2; ++h) {
                    int kt = 2 * kt2 + h;
                    int c = kt * 8 + t;
                    mma8(d0, d1, d2, d3,
                         Hs[r0 + c], Hs[r1 + c], Hs[r0 + c + 4], Hs[r1 + c + 4],
                         h ? bf.z : bf.x, h ? bf.w : bf.y);
                }
            }
            int c = nt * 8 + 2 * t;
            if (e0 < NE) {
                size_t o = ((size_t)(b * NE + e0)) * ED + c;
                float2 xv = *reinterpret_cast<const float2*>(g_xs + o);
                *reinterpret_cast<float2*>(xs_out + o) =
                    make_float2(xv.x + d0, xv.y + d1);
            }
            if (e1 < NE) {
                size_t o = ((size_t)(b * NE + e1)) * ED + c;
                float2 xv = *reinterpret_cast<const float2*>(g_xs + o);
                *reinterpret_cast<float2*>(xs_out + o) =
                    make_float2(xv.x + d2, xv.y + d3);
            }
        }
    }
}

// ---------------------------------------------------------------------------
extern "C" void kernel_launch(void* const* d_in, const int* in_sizes, int n_in,
                              void* d_out, int out_size) {
    const float* dists    = (const float*)d_in[0];
    const float* emb_elec = (const float*)d_in[1];
    const float* emb_nuc  = (const float*)d_in[2];
    const float* kw1      = (const float*)d_in[3];
    const float* kb1      = (const float*)d_in[4];
    const float* kw2      = (const float*)d_in[5];
    const float* kb2      = (const float*)d_in[6];
    const float* eiw      = (const float*)d_in[7];
    const float* ow1      = (const float*)d_in[8];
    const float* ob1      = (const float*)d_in[9];
    const float* ow2      = (const float*)d_in[10];
    const float* ob2      = (const float*)d_in[11];
    float* out = (float*)d_out;

    static int configured = 0;
    if (!configured) {
        cudaFuncSetAttribute(k_layer, cudaFuncAttributeMaxDynamicSharedMemorySize, MS_BYTES);
        configured = 1;
    }
    void* xsptr = nullptr;
    cudaGetSymbolAddress(&xsptr, g_xs);

    k_init<<<4096, 256>>>(emb_elec);
    k_prepack<<<NL, 256>>>(kw1, kw2, ow1, ow2);
    for (int l = 0; l < NL; ++l) {
        float* xs_out = (l == NL - 1) ? out : (float*)xsptr;
        k_layer<<<NB, 256, MS_BYTES>>>(dists, emb_nuc, eiw, kb1, kb2, ob1, ob2,
                                       l, xs_out);
    }
}

// round 13
// speedup vs baseline: 2.5286x; 1.1031x over previous
#include <cuda_runtime.h>

#define NB    2048
#define NE    30
#define NA    38
#define NN    8
#define BASIS 32
#define KD    64
#define ED    128
#define HK    45
#define HO    91
#define NL    3

typedef unsigned long long ull;
typedef unsigned int uint32;

__device__ float g_xs [NB * NE * ED];

// Prepacked tf32 B-fragments, kt-PAIR packed (uint4 = two mma B operands).
__device__ uint4 g_B1f[NL][6 * 2 * 32];     // msg w1  [nt6][kt2:2][lane]
__device__ uint4 g_B2f[NL][8 * 3 * 32];     // msg w2 + b2 row45 [nt8][kt2:3][lane]
__device__ uint4 g_B1o[NL][12 * 4 * 32];    // out W1  [nt12][kt2:4][lane]
__device__ uint4 g_B2o[NL][16 * 6 * 32];    // out W2  [nt16][kt2:6][lane]
__device__ uint4 g_BeH[NL][8 * 8 * 32];     // eiw hi  [nt8][kt2:8][lane]
__device__ uint4 g_BeL[NL][8 * 8 * 32];     // eiw lo  [nt8][kt2:8][lane]

__device__ __forceinline__ float ssp(float x) {
    float t = __expf(-fabsf(x));
    return fmaxf(x, 0.f) + __logf(1.f + t) - 0.69314718055994530942f;
}
__device__ __forceinline__ void sts2(float* p, float x, float y) {
    *reinterpret_cast<float2*>(p) = make_float2(x, y);
}
__device__ __forceinline__ uint32 f2tf(float x) {
    uint32 u; asm("cvt.rna.tf32.f32 %0, %1;" : "=r"(u) : "f"(x)); return u;
}
__device__ __forceinline__ void mma8(float& d0, float& d1, float& d2, float& d3,
                                     uint32 a0, uint32 a1, uint32 a2, uint32 a3,
                                     uint32 b0, uint32 b1) {
    asm volatile(
        "mma.sync.aligned.m16n8k8.row.col.f32.tf32.tf32.f32 "
        "{%0,%1,%2,%3},{%4,%5,%6,%7},{%8,%9},{%0,%1,%2,%3};"
        : "+f"(d0), "+f"(d1), "+f"(d2), "+f"(d3)
        : "r"(a0), "r"(a1), "r"(a2), "r"(a3), "r"(b0), "r"(b1));
}

__global__ void k_init(const float* __restrict__ emb_elec) {
    const int total = NB * NE * ED;
    for (int idx = blockIdx.x * blockDim.x + threadIdx.x; idx < total;
         idx += gridDim.x * blockDim.x) {
        int d = idx % ED, i = (idx / ED) % NE;
        g_xs[idx] = emb_elec[i * ED + d];
    }
}

// ---------------------------------------------------------------------------
// One-time fragment prepack: block l handles layer l.
// uint4 = B rows { ka, ka+4, ka+8, ka+12 }, ka = kt2*16 + t
// ---------------------------------------------------------------------------
__global__ void k_prepack(const float* __restrict__ kw1,
                          const float* __restrict__ kw2,
                          const float* __restrict__ kb2,
                          const float* __restrict__ ow1,
                          const float* __restrict__ ow2,
                          const float* __restrict__ eiw) {
    const int l = blockIdx.x, tid = threadIdx.x;
    const float* w1 = kw1 + (size_t)l * BASIS * HK;
    const float* w2 = kw2 + (size_t)l * HK * KD;
    const float* b2 = kb2 + (size_t)l * KD;
    const float* W1 = ow1 + (size_t)l * KD * HO;
    const float* W2 = ow2 + (size_t)l * HO * ED;
    const float* We = eiw + (size_t)l * ED * KD;

    for (int it = tid; it < 6 * 2 * 32; it += 256) {
        int lane_ = it & 31;
        int kt2 = (it >> 5) & 1;
        int nt  = it >> 6;
        int g_ = lane_ >> 2, t_ = lane_ & 3;
        int n  = nt * 8 + g_;
        int ka = kt2 * 16 + t_;
        bool ok = (n < HK);
        g_B1f[l][it] = make_uint4(f2tf(ok ? w1[ka * HK + n] : 0.f),
                                  f2tf(ok ? w1[(ka + 4) * HK + n] : 0.f),
                                  f2tf(ok ? w1[(ka + 8) * HK + n] : 0.f),
                                  f2tf(ok ? w1[(ka + 12) * HK + n] : 0.f));
    }
    // w2 with bias row: k == 45 -> b2[n]; k > 45 -> 0
    for (int it = tid; it < 8 * 3 * 32; it += 256) {
        int lane_ = it & 31;
        int kt2 = (it >> 5) % 3;
        int nt  = it / 96;
        int g_ = lane_ >> 2, t_ = lane_ & 3;
        int n  = nt * 8 + g_;
        int ka = kt2 * 16 + t_;
        float v[4];
        #pragma unroll
        for (int m = 0; m < 4; ++m) {
            int k = ka + 4 * m;
            v[m] = (k < HK) ? w2[k * KD + n] : ((k == HK) ? b2[n] : 0.f);
        }
        g_B2f[l][it] = make_uint4(f2tf(v[0]), f2tf(v[1]), f2tf(v[2]), f2tf(v[3]));
    }
    for (int it = tid; it < 12 * 4 * 32; it += 256) {
        int lane_ = it & 31;
        int kt2 = (it >> 5) & 3;
        int nt  = it >> 7;
        int g_ = lane_ >> 2, t_ = lane_ & 3;
        int n  = nt * 8 + g_;
        int ka = kt2 * 16 + t_;
        bool ok = (n < HO);
        g_B1o[l][it] = make_uint4(f2tf(ok ? W1[ka * HO + n] : 0.f),
                                  f2tf(ok ? W1[(ka + 4) * HO + n] : 0.f),
                                  f2tf(ok ? W1[(ka + 8) * HO + n] : 0.f),
                                  f2tf(ok ? W1[(ka + 12) * HO + n] : 0.f));
    }
    for (int it = tid; it < 16 * 6 * 32; it += 256) {
        int lane_ = it & 31;
        int kt2 = (it >> 5) % 6;
        int nt  = it / 192;
        int g_ = lane_ >> 2, t_ = lane_ & 3;
        int n  = nt * 8 + g_;
        int ka = kt2 * 16 + t_;
        g_B2o[l][it] = make_uint4(
            f2tf((ka      < HO) ? W2[ka * ED + n] : 0.f),
            f2tf((ka + 4  < HO) ? W2[(ka + 4) * ED + n] : 0.f),
            f2tf((ka + 8  < HO) ? W2[(ka + 8) * ED + n] : 0.f),
            f2tf((ka + 12 < HO) ? W2[(ka + 12) * ED + n] : 0.f));
    }
    // eiw hi/lo split fragments (K=128 -> 8 kt2, N=64 -> 8 nt)
    for (int it = tid; it < 8 * 8 * 32; it += 256) {
        int lane_ = it & 31;
        int kt2 = (it >> 5) & 7;
        int nt  = it >> 8;
        int g_ = lane_ >> 2, t_ = lane_ & 3;
        int n  = nt * 8 + g_;
        int ka = kt2 * 16 + t_;
        uint32 h[4], lo[4];
        #pragma unroll
        for (int m = 0; m < 4; ++m) {
            float v = We[(ka + 4 * m) * KD + n];
            h[m]  = f2tf(v);
            lo[m] = f2tf(v - __uint_as_float(h[m]));
        }
        g_BeH[l][it] = make_uint4(h[0], h[1], h[2], h[3]);
        g_BeL[l][it] = make_uint4(lo[0], lo[1], lo[2], lo[3]);
    }
}

// ---------------------------------------------------------------------------
// k_layer = zs (3xTF32 MMA) + msg (pair MLP, MMA) + fused out MLP (MMA).
// smem (floats):
//   zsv   [0,3456)       zs[j][c], j 0..47 (38..47 zero), stride 72
//   smsg  [3456,5632)    32 rows x stride 68 (rows>=30 zero)
//   scratch [5632,17664)
//     phase1: xs2 30x132 (3960 f) @scratch
//     phase2: B1f uint4[384] @scratch | B2f uint4[768] @scratch+1536
//             H per warp 16x52 @scratch+4608 (+w*832)
//     out:    Hs 32x100 (3200 f) @scratch
//   sb1 [17664,17712) | sb1o [17776,17872) | sb2o [17872,18000)
// ---------------------------------------------------------------------------
#define MS_TOTAL_F 18000
#define MS_BYTES   (MS_TOTAL_F * 4)

__global__ void __launch_bounds__(256, 3) k_layer(
        const float* __restrict__ dists,
        const float* __restrict__ emb_nuc,
        const float* __restrict__ kb1,
        const float* __restrict__ ob1,
        const float* __restrict__ ob2,
        int l, float* __restrict__ xs_out) {
    extern __shared__ float sm[];
    float*  zsv     = sm;
    float*  smsg    = sm + 3456;
    float*  scratch = sm + 5632;
    float*  xs2     = scratch;
    uint4*  B1f     = reinterpret_cast<uint4*>(scratch);           // 384 uint4
    uint4*  B2f     = reinterpret_cast<uint4*>(scratch + 1536);    // 768 uint4
    uint32* Hall    = reinterpret_cast<uint32*>(scratch + 4608);
    uint32* Hs      = reinterpret_cast<uint32*>(scratch);
    float*  sb1     = sm + 17664;
    float*  sb1o    = sm + 17776;
    float*  sb2o    = sm + 17872;

    const int b = blockIdx.x, tid = threadIdx.x;
    const int w = tid >> 5, lane = tid & 31;
    const int g = lane >> 2, t = lane & 3;

    // ---- phase 1a: stage xs (stride 132), nuclear zs, pads, biases ----
    {
        const float* xsb = g_xs + (size_t)b * NE * ED;
        for (int it = tid; it < NE * 64; it += 256) {
            int r = it >> 6, c2 = it & 63;
            float2 v = *reinterpret_cast<const float2*>(xsb + r * ED + 2 * c2);
            *reinterpret_cast<float2*>(xs2 + r * 132 + 2 * c2) = v;
        }
        for (int idx = tid; idx < NN * KD; idx += 256) {
            int n = idx >> 6, c = idx & 63;
            zsv[(NE + n) * 72 + c] = emb_nuc[n * KD + c];
        }
        for (int idx = tid; idx < 10 * 64; idx += 256) {
            int r = idx >> 6, c = idx & 63;
            zsv[(38 + r) * 72 + c] = 0.f;
        }
        for (int idx = tid; idx < 2 * 68; idx += 256)
            smsg[30 * 68 + idx] = 0.f;
        if (tid < 48)  sb1[tid]  = (tid < HK) ? kb1[l * HK + tid] : 0.f;
        if (tid < 96)  sb1o[tid] = (tid < HO) ? ob1[l * HO + tid] : 0.f;
        if (tid < 128) sb2o[tid] = ob2[l * ED + tid];
    }
    __syncthreads();

    // ---- phase 1b: electron zs = xs @ eiw via 3xTF32 MMA (warp w -> nt=w) ----
    {
        float D0[4] = {0.f, 0.f, 0.f, 0.f};
        float D1[4] = {0.f, 0.f, 0.f, 0.f};
        #pragma unroll
        for (int kt2 = 0; kt2 < 8; ++kt2) {
            uint4 bh = __ldg(g_BeH[l] + (w * 8 + kt2) * 32 + lane);
            uint4 bl = __ldg(g_BeL[l] + (w * 8 + kt2) * 32 + lane);
            #pragma unroll
            for (int h = 0; h < 2; ++h) {
                int c = (kt2 * 2 + h) * 8 + t;
                uint32 bx = h ? bh.z : bh.x, by = h ? bh.w : bh.y;
                uint32 lx = h ? bl.z : bl.x, ly = h ? bl.w : bl.y;
                #pragma unroll
                for (int mt = 0; mt < 2; ++mt) {
                    int r0 = mt * 16 + g, r1 = r0 + 8;
                    float x0 = (r0 < NE) ? xs2[r0 * 132 + c] : 0.f;
                    float x1 = (r1 < NE) ? xs2[r1 * 132 + c] : 0.f;
                    float x2 = (r0 < NE) ? xs2[r0 * 132 + c + 4] : 0.f;
                    float x3 = (r1 < NE) ? xs2[r1 * 132 + c + 4] : 0.f;
                    uint32 a0 = f2tf(x0), a1 = f2tf(x1), a2 = f2tf(x2), a3 = f2tf(x3);
                    uint32 e0 = f2tf(x0 - __uint_as_float(a0));
                    uint32 e1 = f2tf(x1 - __uint_as_float(a1));
                    uint32 e2 = f2tf(x2 - __uint_as_float(a2));
                    uint32 e3 = f2tf(x3 - __uint_as_float(a3));
                    float* D = mt ? D1 : D0;
                    mma8(D[0], D[1], D[2], D[3], a0, a1, a2, a3, bx, by);
                    mma8(D[0], D[1], D[2], D[3], a0, a1, a2, a3, lx, ly);
                    mma8(D[0], D[1], D[2], D[3], e0, e1, e2, e3, bx, by);
                }
            }
        }
        #pragma unroll
        for (int mt = 0; mt < 2; ++mt) {
            int r0 = mt * 16 + g, r1 = r0 + 8;
            float* D = mt ? D1 : D0;
            if (r0 < NE) sts2(zsv + r0 * 72 + w * 8 + 2 * t, D[0], D[1]);
            if (r1 < NE) sts2(zsv + r1 * 72 + w * 8 + 2 * t, D[2], D[3]);
        }
    }
    __syncthreads();

    // ---- phase 2a: copy prepacked msg B-fragments into smem (uint4) ----
    {
        const uint4* s1 = g_B1f[l];
        for (int it = tid; it < 384; it += 256) B1f[it] = s1[it];
        const uint4* s2 = g_B2f[l];
        for (int it = tid; it < 768; it += 256) B2f[it] = s2[it];
    }
    __syncthreads();

    uint32* Hw = Hall + w * 832;

    // ---- main loop: pair MLP + j-sum -> smsg ----
    for (int i = w; i < NE; i += 8) {
        const float* dbase = dists + ((size_t)(b * NE + i)) * NA * BASIS;
        float macc[16];
        #pragma unroll
        for (int r = 0; r < 16; ++r) macc[r] = 0.f;

        #pragma unroll
        for (int mt = 0; mt < 3; ++mt) {
            const int j0 = mt * 16 + g, j1 = j0 + 8;

            uint32 A1[4][4];
            #pragma unroll
            for (int kt = 0; kt < 4; ++kt) {
                int k0 = kt * 8 + t;
                float a0 = (j0 < NA) ? __ldg(dbase + j0 * BASIS + k0) : 0.f;
                float a1 = (j1 < NA) ? __ldg(dbase + j1 * BASIS + k0) : 0.f;
                float a2 = (j0 < NA) ? __ldg(dbase + j0 * BASIS + k0 + 4) : 0.f;
                float a3 = (j1 < NA) ? __ldg(dbase + j1 * BASIS + k0 + 4) : 0.f;
                A1[kt][0] = f2tf(a0); A1[kt][1] = f2tf(a1);
                A1[kt][2] = f2tf(a2); A1[kt][3] = f2tf(a3);
            }

            #pragma unroll
            for (int nt = 0; nt < 6; ++nt) {
                float2 bb = *reinterpret_cast<const float2*>(sb1 + nt * 8 + 2 * t);
                float d0 = bb.x, d1 = bb.y, d2 = bb.x, d3 = bb.y;
                const uint4* bp = B1f + nt * 64 + lane;
                #pragma unroll
                for (int kt2 = 0; kt2 < 2; ++kt2) {
                    uint4 bf = bp[kt2 * 32];
                    mma8(d0, d1, d2, d3,
                         A1[2 * kt2][0], A1[2 * kt2][1], A1[2 * kt2][2], A1[2 * kt2][3],
                         bf.x, bf.y);
                    mma8(d0, d1, d2, d3,
                         A1[2 * kt2 + 1][0], A1[2 * kt2 + 1][1], A1[2 * kt2 + 1][2], A1[2 * kt2 + 1][3],
                         bf.z, bf.w);
                }
                uint2 lo = make_uint2(f2tf(ssp(d0)), f2tf(ssp(d1)));
                uint2 hi = make_uint2(f2tf(ssp(d2)), f2tf(ssp(d3)));
                if (nt == 5 && t == 2) {   // H col 45 := 1.0 (bias K-row)
                    lo.y = 0x3f800000u;
                    hi.y = 0x3f800000u;
                }
                *reinterpret_cast<uint2*>(Hw + g * 52 + nt * 8 + 2 * t)       = lo;
                *reinterpret_cast<uint2*>(Hw + (g + 8) * 52 + nt * 8 + 2 * t) = hi;
            }
            __syncwarp();

            uint32 A2[6][4];
            #pragma unroll
            for (int kt = 0; kt < 6; ++kt) {
                A2[kt][0] = Hw[g * 52 + kt * 8 + t];
                A2[kt][1] = Hw[(g + 8) * 52 + kt * 8 + t];
                A2[kt][2] = Hw[g * 52 + kt * 8 + t + 4];
                A2[kt][3] = Hw[(g + 8) * 52 + kt * 8 + t + 4];
            }
            const float pm0 = (j0 != i) ? 1.f : 0.f;
            const float pm1 = (j1 != i) ? 1.f : 0.f;

            #pragma unroll
            for (int nt = 0; nt < 8; ++nt) {
                float d0 = 0.f, d1 = 0.f, d2 = 0.f, d3 = 0.f;   // bias via K-row 45
                const uint4* bp = B2f + nt * 96 + lane;
                #pragma unroll
                for (int kt2 = 0; kt2 < 3; ++kt2) {
                    uint4 bf = bp[kt2 * 32];
                    mma8(d0, d1, d2, d3,
                         A2[2 * kt2][0], A2[2 * kt2][1], A2[2 * kt2][2], A2[2 * kt2][3],
                         bf.x, bf.y);
                    mma8(d0, d1, d2, d3,
                         A2[2 * kt2 + 1][0], A2[2 * kt2 + 1][1], A2[2 * kt2 + 1][2], A2[2 * kt2 + 1][3],
                         bf.z, bf.w);
                }
                float2 z0 = *reinterpret_cast<const float2*>(zsv + j0 * 72 + nt * 8 + 2 * t);
                float2 z1 = *reinterpret_cast<const float2*>(zsv + j1 * 72 + nt * 8 + 2 * t);
                macc[2 * nt]     += pm0 * d0 * z0.x + pm1 * d2 * z1.x;
                macc[2 * nt + 1] += pm0 * d1 * z0.y + pm1 * d3 * z1.y;
            }
            __syncwarp();
        }

        #pragma unroll
        for (int r = 0; r < 16; ++r) {
            macc[r] += __shfl_xor_sync(0xffffffffu, macc[r], 4);
            macc[r] += __shfl_xor_sync(0xffffffffu, macc[r], 8);
            macc[r] += __shfl_xor_sync(0xffffffffu, macc[r], 16);
        }
        if (g == 0) {
            #pragma unroll
            for (int nt = 0; nt < 8; ++nt)
                sts2(smsg + i * 68 + nt * 8 + 2 * t, macc[2 * nt], macc[2 * nt + 1]);
        }
    }
    __syncthreads();   // smsg complete; scratch (B1f/B2f/H) now dead

    // ---- out GEMM1: Hs = ssp(msg @ W1 + b1); warp covers nt = w, w+8 ----
    #pragma unroll
    for (int mt = 0; mt < 2; ++mt) {
        int r0 = (mt * 16 + g) * 68, r1 = (mt * 16 + g + 8) * 68;
        #pragma unroll
        for (int rep = 0; rep < 2; ++rep) {
            int nt = w + 8 * rep;
            if (nt < 12) {
                float2 bb = *reinterpret_cast<const float2*>(sb1o + nt * 8 + 2 * t);
                float d0 = bb.x, d1 = bb.y, d2 = bb.x, d3 = bb.y;
                const uint4* bp = g_B1o[l] + nt * 128 + lane;
                #pragma unroll
                for (int kt2 = 0; kt2 < 4; ++kt2) {
                    uint4 bf = __ldg(bp + kt2 * 32);
                    #pragma unroll
                    for (int h = 0; h < 2; ++h) {
                        int kt = 2 * kt2 + h;
                        int c = kt * 8 + t;
                        uint32 a0 = f2tf(smsg[r0 + c]);
                        uint32 a1 = f2tf(smsg[r1 + c]);
                        uint32 a2 = f2tf(smsg[r0 + c + 4]);
                        uint32 a3 = f2tf(smsg[r1 + c + 4]);
                        mma8(d0, d1, d2, d3, a0, a1, a2, a3,
                             h ? bf.z : bf.x, h ? bf.w : bf.y);
                    }
                }
                int c = nt * 8 + 2 * t;
                *reinterpret_cast<uint2*>(Hs + (mt * 16 + g) * 100 + c) =
                    make_uint2(f2tf(ssp(d0)), f2tf(ssp(d1)));
                *reinterpret_cast<uint2*>(Hs + (mt * 16 + g + 8) * 100 + c) =
                    make_uint2(f2tf(ssp(d2)), f2tf(ssp(d3)));
            }
        }
    }
    __syncthreads();

    // ---- out GEMM2 + residual: xs_out = xs + Hs @ W2 + b2; nt = 2w, 2w+1 ----
    #pragma unroll
    for (int mt = 0; mt < 2; ++mt) {
        int r0 = (mt * 16 + g) * 100, r1 = (mt * 16 + g + 8) * 100;
        int e0 = mt * 16 + g, e1 = e0 + 8;
        #pragma unroll
        for (int idx = 0; idx < 2; ++idx) {
            int nt = 2 * w + idx;
            float2 bb = *reinterpret_cast<const float2*>(sb2o + nt * 8 + 2 * t);
            float d0 = bb.x, d1 = bb.y, d2 = bb.x, d3 = bb.y;
            const uint4* bp = g_B2o[l] + nt * 192 + lane;
            #pragma unroll
            for (int kt2 = 0; kt2 < 6; ++kt2) {
                uint4 bf = __ldg(bp + kt2 * 32);
                #pragma unroll
                for (int h = 0; h < 2; ++h) {
                    int kt = 2 * kt2 + h;
                    int c = kt * 8 + t;
                    mma8(d0, d1, d2, d3,
                         Hs[r0 + c], Hs[r1 + c], Hs[r0 + c + 4], Hs[r1 + c + 4],
                         h ? bf.z : bf.x, h ? bf.w : bf.y);
                }
            }
            int c = nt * 8 + 2 * t;
            if (e0 < NE) {
                size_t o = ((size_t)(b * NE + e0)) * ED + c;
                float2 xv = *reinterpret_cast<const float2*>(g_xs + o);
                *reinterpret_cast<float2*>(xs_out + o) =
                    make_float2(xv.x + d0, xv.y + d1);
            }
            if (e1 < NE) {
                size_t o = ((size_t)(b * NE + e1)) * ED + c;
                float2 xv = *reinterpret_cast<const float2*>(g_xs + o);
                *reinterpret_cast<float2*>(xs_out + o) =
                    make_float2(xv.x + d2, xv.y + d3);
            }
        }
    }
}

// ---------------------------------------------------------------------------
extern "C" void kernel_launch(void* const* d_in, const int* in_sizes, int n_in,
                              void* d_out, int out_size) {
    const float* dists    = (const float*)d_in[0];
    const float* emb_elec = (const float*)d_in[1];
    const float* emb_nuc  = (const float*)d_in[2];
    const float* kw1      = (const float*)d_in[3];
    const float* kb1      = (const float*)d_in[4];
    const float* kw2      = (const float*)d_in[5];
    const float* kb2      = (const float*)d_in[6];
    const float* eiw      = (const float*)d_in[7];
    const float* ow1      = (const float*)d_in[8];
    const float* ob1      = (const float*)d_in[9];
    const float* ow2      = (const float*)d_in[10];
    const float* ob2      = (const float*)d_in[11];
    float* out = (float*)d_out;

    static int configured = 0;
    if (!configured) {
        cudaFuncSetAttribute(k_layer, cudaFuncAttributeMaxDynamicSharedMemorySize, MS_BYTES);
        configured = 1;
    }
    void* xsptr = nullptr;
    cudaGetSymbolAddress(&xsptr, g_xs);

    k_init<<<4096, 256>>>(emb_elec);
    k_prepack<<<NL, 256>>>(kw1, kw2, kb2, ow1, ow2, eiw);
    for (int l = 0; l < NL; ++l) {
        float* xs_out = (l == NL - 1) ? out : (float*)xsptr;
        k_layer<<<NB, 256, MS_BYTES>>>(dists, emb_nuc, kb1, ob1, ob2, l, xs_out);
    }
}

// round 14
// speedup vs baseline: 2.8285x; 1.1186x over previous
#include <cuda_runtime.h>

#define NB    2048
#define NE    30
#define NA    38
#define NN    8
#define BASIS 32
#define KD    64
#define ED    128
#define HK    45
#define HO    91
#define NL    3

typedef unsigned long long ull;
typedef unsigned int uint32;

__device__ float g_xs [NB * NE * ED];

// Prepacked tf32 B-fragments, kt-PAIR packed (uint4 = two mma B operands).
// B1f uses sigma-permuted K: fragment (kt,t) -> w1 rows {4t+kt, 16+4t+kt}.
__device__ uint4 g_B1f[NL][6 * 2 * 32];     // msg w1  [nt6][kt2:2][lane]
__device__ uint4 g_B2f[NL][8 * 3 * 32];     // msg w2 + b2 row45 [nt8][kt2:3][lane]
__device__ uint4 g_B1o[NL][12 * 4 * 32];    // out W1  [nt12][kt2:4][lane]
__device__ uint4 g_B2o[NL][16 * 6 * 32];    // out W2  [nt16][kt2:6][lane]
__device__ uint4 g_BeH[NL][8 * 8 * 32];     // eiw hi  [nt8][kt2:8][lane]
__device__ uint4 g_BeL[NL][8 * 8 * 32];     // eiw lo  [nt8][kt2:8][lane]

__device__ __forceinline__ float ssp(float x) {
    float t = __expf(-fabsf(x));
    return fmaxf(x, 0.f) + __logf(1.f + t) - 0.69314718055994530942f;
}
__device__ __forceinline__ void sts2(float* p, float x, float y) {
    *reinterpret_cast<float2*>(p) = make_float2(x, y);
}
__device__ __forceinline__ uint32 f2tf(float x) {
    uint32 u; asm("cvt.rna.tf32.f32 %0, %1;" : "=r"(u) : "f"(x)); return u;
}
__device__ __forceinline__ void mma8(float& d0, float& d1, float& d2, float& d3,
                                     uint32 a0, uint32 a1, uint32 a2, uint32 a3,
                                     uint32 b0, uint32 b1) {
    asm volatile(
        "mma.sync.aligned.m16n8k8.row.col.f32.tf32.tf32.f32 "
        "{%0,%1,%2,%3},{%4,%5,%6,%7},{%8,%9},{%0,%1,%2,%3};"
        : "+f"(d0), "+f"(d1), "+f"(d2), "+f"(d3)
        : "r"(a0), "r"(a1), "r"(a2), "r"(a3), "r"(b0), "r"(b1));
}

__global__ void k_init(const float* __restrict__ emb_elec) {
    const int total = NB * NE * ED;
    for (int idx = blockIdx.x * blockDim.x + threadIdx.x; idx < total;
         idx += gridDim.x * blockDim.x) {
        int d = idx % ED, i = (idx / ED) % NE;
        g_xs[idx] = emb_elec[i * ED + d];
    }
}

// ---------------------------------------------------------------------------
// One-time fragment prepack: block l handles layer l.
// Default layout: uint4 = B rows { ka, ka+4, ka+8, ka+12 }, ka = kt2*16 + t
// B1f (sigma): uint4 = w1 rows { 4t+2kt2, 16+4t+2kt2, 4t+2kt2+1, 16+4t+2kt2+1 }
// ---------------------------------------------------------------------------
__global__ void k_prepack(const float* __restrict__ kw1,
                          const float* __restrict__ kw2,
                          const float* __restrict__ kb2,
                          const float* __restrict__ ow1,
                          const float* __restrict__ ow2,
                          const float* __restrict__ eiw) {
    const int l = blockIdx.x, tid = threadIdx.x;
    const float* w1 = kw1 + (size_t)l * BASIS * HK;
    const float* w2 = kw2 + (size_t)l * HK * KD;
    const float* b2 = kb2 + (size_t)l * KD;
    const float* W1 = ow1 + (size_t)l * KD * HO;
    const float* W2 = ow2 + (size_t)l * HO * ED;
    const float* We = eiw + (size_t)l * ED * KD;

    // B1f with sigma-permuted K for coalesced float4 A-loads
    for (int it = tid; it < 6 * 2 * 32; it += 256) {
        int lane_ = it & 31;
        int kt2 = (it >> 5) & 1;
        int nt  = it >> 6;
        int g_ = lane_ >> 2, t_ = lane_ & 3;
        int n  = nt * 8 + g_;
        bool ok = (n < HK);
        int kt0 = 2 * kt2, kt1 = kt0 + 1;
        g_B1f[l][it] = make_uint4(
            f2tf(ok ? w1[(4 * t_ + kt0) * HK + n] : 0.f),
            f2tf(ok ? w1[(16 + 4 * t_ + kt0) * HK + n] : 0.f),
            f2tf(ok ? w1[(4 * t_ + kt1) * HK + n] : 0.f),
            f2tf(ok ? w1[(16 + 4 * t_ + kt1) * HK + n] : 0.f));
    }
    // w2 with bias row: k == 45 -> b2[n]; k > 45 -> 0
    for (int it = tid; it < 8 * 3 * 32; it += 256) {
        int lane_ = it & 31;
        int kt2 = (it >> 5) % 3;
        int nt  = it / 96;
        int g_ = lane_ >> 2, t_ = lane_ & 3;
        int n  = nt * 8 + g_;
        int ka = kt2 * 16 + t_;
        float v[4];
        #pragma unroll
        for (int m = 0; m < 4; ++m) {
            int k = ka + 4 * m;
            v[m] = (k < HK) ? w2[k * KD + n] : ((k == HK) ? b2[n] : 0.f);
        }
        g_B2f[l][it] = make_uint4(f2tf(v[0]), f2tf(v[1]), f2tf(v[2]), f2tf(v[3]));
    }
    for (int it = tid; it < 12 * 4 * 32; it += 256) {
        int lane_ = it & 31;
        int kt2 = (it >> 5) & 3;
        int nt  = it >> 7;
        int g_ = lane_ >> 2, t_ = lane_ & 3;
        int n  = nt * 8 + g_;
        int ka = kt2 * 16 + t_;
        bool ok = (n < HO);
        g_B1o[l][it] = make_uint4(f2tf(ok ? W1[ka * HO + n] : 0.f),
                                  f2tf(ok ? W1[(ka + 4) * HO + n] : 0.f),
                                  f2tf(ok ? W1[(ka + 8) * HO + n] : 0.f),
                                  f2tf(ok ? W1[(ka + 12) * HO + n] : 0.f));
    }
    for (int it = tid; it < 16 * 6 * 32; it += 256) {
        int lane_ = it & 31;
        int kt2 = (it >> 5) % 6;
        int nt  = it / 192;
        int g_ = lane_ >> 2, t_ = lane_ & 3;
        int n  = nt * 8 + g_;
        int ka = kt2 * 16 + t_;
        g_B2o[l][it] = make_uint4(
            f2tf((ka      < HO) ? W2[ka * ED + n] : 0.f),
            f2tf((ka + 4  < HO) ? W2[(ka + 4) * ED + n] : 0.f),
            f2tf((ka + 8  < HO) ? W2[(ka + 8) * ED + n] : 0.f),
            f2tf((ka + 12 < HO) ? W2[(ka + 12) * ED + n] : 0.f));
    }
    // eiw hi/lo split fragments (K=128 -> 8 kt2, N=64 -> 8 nt)
    for (int it = tid; it < 8 * 8 * 32; it += 256) {
        int lane_ = it & 31;
        int kt2 = (it >> 5) & 7;
        int nt  = it >> 8;
        int g_ = lane_ >> 2, t_ = lane_ & 3;
        int n  = nt * 8 + g_;
        int ka = kt2 * 16 + t_;
        uint32 h[4], lo[4];
        #pragma unroll
        for (int m = 0; m < 4; ++m) {
            float v = We[(ka + 4 * m) * KD + n];
            h[m]  = f2tf(v);
            lo[m] = f2tf(v - __uint_as_float(h[m]));
        }
        g_BeH[l][it] = make_uint4(h[0], h[1], h[2], h[3]);
        g_BeL[l][it] = make_uint4(lo[0], lo[1], lo[2], lo[3]);
    }
}

// ---------------------------------------------------------------------------
// k_layer = zs (3xTF32 MMA) + msg (pair MLP, MMA) + fused out MLP (MMA).
// smem map identical to R12.
// ---------------------------------------------------------------------------
#define MS_TOTAL_F 18000
#define MS_BYTES   (MS_TOTAL_F * 4)

__global__ void __launch_bounds__(256, 3) k_layer(
        const float* __restrict__ dists,
        const float* __restrict__ emb_nuc,
        const float* __restrict__ kb1,
        const float* __restrict__ ob1,
        const float* __restrict__ ob2,
        int l, float* __restrict__ xs_out) {
    extern __shared__ float sm[];
    float*  zsv     = sm;
    float*  smsg    = sm + 3456;
    float*  scratch = sm + 5632;
    float*  xs2     = scratch;
    uint4*  B1f     = reinterpret_cast<uint4*>(scratch);           // 384 uint4
    uint4*  B2f     = reinterpret_cast<uint4*>(scratch + 1536);    // 768 uint4
    uint32* Hall    = reinterpret_cast<uint32*>(scratch + 4608);
    uint32* Hs      = reinterpret_cast<uint32*>(scratch);
    float*  sb1     = sm + 17664;
    float*  sb1o    = sm + 17776;
    float*  sb2o    = sm + 17872;

    const int b = blockIdx.x, tid = threadIdx.x;
    const int w = tid >> 5, lane = tid & 31;
    const int g = lane >> 2, t = lane & 3;

    // ---- phase 1a: stage xs (stride 132), nuclear zs, pads, biases ----
    {
        const float* xsb = g_xs + (size_t)b * NE * ED;
        for (int it = tid; it < NE * 64; it += 256) {
            int r = it >> 6, c2 = it & 63;
            float2 v = *reinterpret_cast<const float2*>(xsb + r * ED + 2 * c2);
            *reinterpret_cast<float2*>(xs2 + r * 132 + 2 * c2) = v;
        }
        for (int idx = tid; idx < NN * KD; idx += 256) {
            int n = idx >> 6, c = idx & 63;
            zsv[(NE + n) * 72 + c] = emb_nuc[n * KD + c];
        }
        for (int idx = tid; idx < 10 * 64; idx += 256) {
            int r = idx >> 6, c = idx & 63;
            zsv[(38 + r) * 72 + c] = 0.f;
        }
        for (int idx = tid; idx < 2 * 68; idx += 256)
            smsg[30 * 68 + idx] = 0.f;
        if (tid < 48)  sb1[tid]  = (tid < HK) ? kb1[l * HK + tid] : 0.f;
        if (tid < 96)  sb1o[tid] = (tid < HO) ? ob1[l * HO + tid] : 0.f;
        if (tid < 128) sb2o[tid] = ob2[l * ED + tid];
    }
    __syncthreads();

    // ---- phase 1b: electron zs = xs @ eiw via 3xTF32 MMA (warp w -> nt=w) ----
    {
        float D0[4] = {0.f, 0.f, 0.f, 0.f};
        float D1[4] = {0.f, 0.f, 0.f, 0.f};
        #pragma unroll
        for (int kt2 = 0; kt2 < 8; ++kt2) {
            uint4 bh = __ldg(g_BeH[l] + (w * 8 + kt2) * 32 + lane);
            uint4 bl = __ldg(g_BeL[l] + (w * 8 + kt2) * 32 + lane);
            #pragma unroll
            for (int h = 0; h < 2; ++h) {
                int c = (kt2 * 2 + h) * 8 + t;
                uint32 bx = h ? bh.z : bh.x, by = h ? bh.w : bh.y;
                uint32 lx = h ? bl.z : bl.x, ly = h ? bl.w : bl.y;
                #pragma unroll
                for (int mt = 0; mt < 2; ++mt) {
                    int r0 = mt * 16 + g, r1 = r0 + 8;
                    float x0 = (r0 < NE) ? xs2[r0 * 132 + c] : 0.f;
                    float x1 = (r1 < NE) ? xs2[r1 * 132 + c] : 0.f;
                    float x2 = (r0 < NE) ? xs2[r0 * 132 + c + 4] : 0.f;
                    float x3 = (r1 < NE) ? xs2[r1 * 132 + c + 4] : 0.f;
                    uint32 a0 = f2tf(x0), a1 = f2tf(x1), a2 = f2tf(x2), a3 = f2tf(x3);
                    uint32 e0 = f2tf(x0 - __uint_as_float(a0));
                    uint32 e1 = f2tf(x1 - __uint_as_float(a1));
                    uint32 e2 = f2tf(x2 - __uint_as_float(a2));
                    uint32 e3 = f2tf(x3 - __uint_as_float(a3));
                    float* D = mt ? D1 : D0;
                    mma8(D[0], D[1], D[2], D[3], a0, a1, a2, a3, bx, by);
                    mma8(D[0], D[1], D[2], D[3], a0, a1, a2, a3, lx, ly);
                    mma8(D[0], D[1], D[2], D[3], e0, e1, e2, e3, bx, by);
                }
            }
        }
        #pragma unroll
        for (int mt = 0; mt < 2; ++mt) {
            int r0 = mt * 16 + g, r1 = r0 + 8;
            float* D = mt ? D1 : D0;
            if (r0 < NE) sts2(zsv + r0 * 72 + w * 8 + 2 * t, D[0], D[1]);
            if (r1 < NE) sts2(zsv + r1 * 72 + w * 8 + 2 * t, D[2], D[3]);
        }
    }
    __syncthreads();

    // ---- phase 2a: copy prepacked msg B-fragments into smem (uint4) ----
    {
        const uint4* s1 = g_B1f[l];
        for (int it = tid; it < 384; it += 256) B1f[it] = s1[it];
        const uint4* s2 = g_B2f[l];
        for (int it = tid; it < 768; it += 256) B2f[it] = s2[it];
    }
    __syncthreads();

    uint32* Hw = Hall + w * 832;

    // ---- main loop: pair MLP + j-sum -> smsg ----
    for (int i = w; i < NE; i += 8) {
        const float* dbase = dists + ((size_t)(b * NE + i)) * NA * BASIS;
        float macc[16];
        #pragma unroll
        for (int r = 0; r < 16; ++r) macc[r] = 0.f;

        #pragma unroll
        for (int mt = 0; mt < 3; ++mt) {
            const int j0 = mt * 16 + g, j1 = j0 + 8;

            // A1 via coalesced float4 loads (sigma-permuted K, matches B1f)
            const float4 zf4 = make_float4(0.f, 0.f, 0.f, 0.f);
            float4 l0 = (j0 < NA) ? __ldg(reinterpret_cast<const float4*>(dbase + j0 * BASIS + 4 * t)) : zf4;
            float4 h0 = (j0 < NA) ? __ldg(reinterpret_cast<const float4*>(dbase + j0 * BASIS + 16 + 4 * t)) : zf4;
            float4 l1 = (j1 < NA) ? __ldg(reinterpret_cast<const float4*>(dbase + j1 * BASIS + 4 * t)) : zf4;
            float4 h1 = (j1 < NA) ? __ldg(reinterpret_cast<const float4*>(dbase + j1 * BASIS + 16 + 4 * t)) : zf4;
            const float* pl0 = reinterpret_cast<const float*>(&l0);
            const float* ph0 = reinterpret_cast<const float*>(&h0);
            const float* pl1 = reinterpret_cast<const float*>(&l1);
            const float* ph1 = reinterpret_cast<const float*>(&h1);
            uint32 A1[4][4];
            #pragma unroll
            for (int kt = 0; kt < 4; ++kt) {
                A1[kt][0] = f2tf(pl0[kt]);   // db[j0][4t+kt]
                A1[kt][1] = f2tf(pl1[kt]);   // db[j1][4t+kt]
                A1[kt][2] = f2tf(ph0[kt]);   // db[j0][16+4t+kt]
                A1[kt][3] = f2tf(ph1[kt]);   // db[j1][16+4t+kt]
            }

            #pragma unroll
            for (int nt = 0; nt < 6; ++nt) {
                float2 bb = *reinterpret_cast<const float2*>(sb1 + nt * 8 + 2 * t);
                float d0 = bb.x, d1 = bb.y, d2 = bb.x, d3 = bb.y;
                const uint4* bp = B1f + nt * 64 + lane;
                #pragma unroll
                for (int kt2 = 0; kt2 < 2; ++kt2) {
                    uint4 bf = bp[kt2 * 32];
                    mma8(d0, d1, d2, d3,
                         A1[2 * kt2][0], A1[2 * kt2][1], A1[2 * kt2][2], A1[2 * kt2][3],
                         bf.x, bf.y);
                    mma8(d0, d1, d2, d3,
                         A1[2 * kt2 + 1][0], A1[2 * kt2 + 1][1], A1[2 * kt2 + 1][2], A1[2 * kt2 + 1][3],
                         bf.z, bf.w);
                }
                uint2 lo = make_uint2(f2tf(ssp(d0)), f2tf(ssp(d1)));
                uint2 hi = make_uint2(f2tf(ssp(d2)), f2tf(ssp(d3)));
                if (nt == 5 && t == 2) {   // H col 45 := 1.0 (bias K-row)
                    lo.y = 0x3f800000u;
                    hi.y = 0x3f800000u;
                }
                *reinterpret_cast<uint2*>(Hw + g * 52 + nt * 8 + 2 * t)       = lo;
                *reinterpret_cast<uint2*>(Hw + (g + 8) * 52 + nt * 8 + 2 * t) = hi;
            }
            __syncwarp();

            uint32 A2[6][4];
            #pragma unroll
            for (int kt = 0; kt < 6; ++kt) {
                A2[kt][0] = Hw[g * 52 + kt * 8 + t];
                A2[kt][1] = Hw[(g + 8) * 52 + kt * 8 + t];
                A2[kt][2] = Hw[g * 52 + kt * 8 + t + 4];
                A2[kt][3] = Hw[(g + 8) * 52 + kt * 8 + t + 4];
            }
            const float pm0 = (j0 != i) ? 1.f : 0.f;
            const float pm1 = (j1 != i) ? 1.f : 0.f;

            #pragma unroll
            for (int nt = 0; nt < 8; ++nt) {
                float d0 = 0.f, d1 = 0.f, d2 = 0.f, d3 = 0.f;   // bias via K-row 45
                const uint4* bp = B2f + nt * 96 + lane;
                #pragma unroll
                for (int kt2 = 0; kt2 < 3; ++kt2) {
                    uint4 bf = bp[kt2 * 32];
                    mma8(d0, d1, d2, d3,
                         A2[2 * kt2][0], A2[2 * kt2][1], A2[2 * kt2][2], A2[2 * kt2][3],
                         bf.x, bf.y);
                    mma8(d0, d1, d2, d3,
                         A2[2 * kt2 + 1][0], A2[2 * kt2 + 1][1], A2[2 * kt2 + 1][2], A2[2 * kt2 + 1][3],
                         bf.z, bf.w);
                }
                float2 z0 = *reinterpret_cast<const float2*>(zsv + j0 * 72 + nt * 8 + 2 * t);
                float2 z1 = *reinterpret_cast<const float2*>(zsv + j1 * 72 + nt * 8 + 2 * t);
                macc[2 * nt]     += pm0 * d0 * z0.x + pm1 * d2 * z1.x;
                macc[2 * nt + 1] += pm0 * d1 * z0.y + pm1 * d3 * z1.y;
            }
            __syncwarp();
        }

        #pragma unroll
        for (int r = 0; r < 16; ++r) {
            macc[r] += __shfl_xor_sync(0xffffffffu, macc[r], 4);
            macc[r] += __shfl_xor_sync(0xffffffffu, macc[r], 8);
            macc[r] += __shfl_xor_sync(0xffffffffu, macc[r], 16);
        }
        if (g == 0) {
            #pragma unroll
            for (int nt = 0; nt < 8; ++nt)
                sts2(smsg + i * 68 + nt * 8 + 2 * t, macc[2 * nt], macc[2 * nt + 1]);
        }
    }
    __syncthreads();   // smsg complete; scratch (B1f/B2f/H) now dead

    // ---- out GEMM1: Hs = ssp(msg @ W1 + b1); warp covers nt = w, w+8 ----
    #pragma unroll
    for (int mt = 0; mt < 2; ++mt) {
        int r0 = (mt * 16 + g) * 68, r1 = (mt * 16 + g + 8) * 68;
        #pragma unroll
        for (int rep = 0; rep < 2; ++rep) {
            int nt = w + 8 * rep;
            if (nt < 12) {
                float2 bb = *reinterpret_cast<const float2*>(sb1o + nt * 8 + 2 * t);
                float d0 = bb.x, d1 = bb.y, d2 = bb.x, d3 = bb.y;
                const uint4* bp = g_B1o[l] + nt * 128 + lane;
                #pragma unroll
                for (int kt2 = 0; kt2 < 4; ++kt2) {
                    uint4 bf = __ldg(bp + kt2 * 32);
                    #pragma unroll
                    for (int h = 0; h < 2; ++h) {
                        int kt = 2 * kt2 + h;
                        int c = kt * 8 + t;
                        uint32 a0 = f2tf(smsg[r0 + c]);
                        uint32 a1 = f2tf(smsg[r1 + c]);
                        uint32 a2 = f2tf(smsg[r0 + c + 4]);
                        uint32 a3 = f2tf(smsg[r1 + c + 4]);
                        mma8(d0, d1, d2, d3, a0, a1, a2, a3,
                             h ? bf.z : bf.x, h ? bf.w : bf.y);
                    }
                }
                int c = nt * 8 + 2 * t;
                *reinterpret_cast<uint2*>(Hs + (mt * 16 + g) * 100 + c) =
                    make_uint2(f2tf(ssp(d0)), f2tf(ssp(d1)));
                *reinterpret_cast<uint2*>(Hs + (mt * 16 + g + 8) * 100 + c) =
                    make_uint2(f2tf(ssp(d2)), f2tf(ssp(d3)));
            }
        }
    }
    __syncthreads();

    // ---- out GEMM2 + residual: xs_out = xs + Hs @ W2 + b2; nt = 2w, 2w+1 ----
    #pragma unroll
    for (int mt = 0; mt < 2; ++mt) {
        int r0 = (mt * 16 + g) * 100, r1 = (mt * 16 + g + 8) * 100;
        int e0 = mt * 16 + g, e1 = e0 + 8;
        #pragma unroll
        for (int idx = 0; idx < 2; ++idx) {
            int nt = 2 * w + idx;
            float2 bb = *reinterpret_cast<const float2*>(sb2o + nt * 8 + 2 * t);
            float d0 = bb.x, d1 = bb.y, d2 = bb.x, d3 = bb.y;
            const uint4* bp = g_B2o[l] + nt * 192 + lane;
            #pragma unroll
            for (int kt2 = 0; kt2 < 6; ++kt2) {
                uint4 bf = __ldg(bp + kt2 * 32);
                #pragma unroll
                for (int h = 0; h < 2; ++h) {
                    int kt = 2 * kt2 + h;
                    int c = kt * 8 + t;
                    mma8(d0, d1, d2, d3,
                         Hs[r0 + c], Hs[r1 + c], Hs[r0 + c + 4], Hs[r1 + c + 4],
                         h ? bf.z : bf.x, h ? bf.w : bf.y);
                }
            }
            int c = nt * 8 + 2 * t;
            if (e0 < NE) {
                size_t o = ((size_t)(b * NE + e0)) * ED + c;
                float2 xv = *reinterpret_cast<const float2*>(g_xs + o);
                *reinterpret_cast<float2*>(xs_out + o) =
                    make_float2(xv.x + d0, xv.y + d1);
            }
            if (e1 < NE) {
                size_t o = ((size_t)(b * NE + e1)) * ED + c;
                float2 xv = *reinterpret_cast<const float2*>(g_xs + o);
                *reinterpret_cast<float2*>(xs_out + o) =
                    make_float2(xv.x + d2, xv.y + d3);
            }
        }
    }
}

// ---------------------------------------------------------------------------
extern "C" void kernel_launch(void* const* d_in, const int* in_sizes, int n_in,
                              void* d_out, int out_size) {
    const float* dists    = (const float*)d_in[0];
    const float* emb_elec = (const float*)d_in[1];
    const float* emb_nuc  = (const float*)d_in[2];
    const float* kw1      = (const float*)d_in[3];
    const float* kb1      = (const float*)d_in[4];
    const float* kw2      = (const float*)d_in[5];
    const float* kb2      = (const float*)d_in[6];
    const float* eiw      = (const float*)d_in[7];
    const float* ow1      = (const float*)d_in[8];
    const float* ob1      = (const float*)d_in[9];
    const float* ow2      = (const float*)d_in[10];
    const float* ob2      = (const float*)d_in[11];
    float* out = (float*)d_out;

    static int configured = 0;
    if (!configured) {
        cudaFuncSetAttribute(k_layer, cudaFuncAttributeMaxDynamicSharedMemorySize, MS_BYTES);
        configured = 1;
    }
    void* xsptr = nullptr;
    cudaGetSymbolAddress(&xsptr, g_xs);

    k_init<<<4096, 256>>>(emb_elec);
    k_prepack<<<NL, 256>>>(kw1, kw2, kb2, ow1, ow2, eiw);
    for (int l = 0; l < NL; ++l) {
        float* xs_out = (l == NL - 1) ? out : (float*)xsptr;
        k_layer<<<NB, 256, MS_BYTES>>>(dists, emb_nuc, kb1, ob1, ob2, l, xs_out);
    }
}